// round 1
// baseline (speedup 1.0000x reference)
#include <cuda_runtime.h>
#include <math.h>
#include <stdint.h>

#define HW      56
#define NPIX    3136          // 56*56
#define CDIM    256
#define HEADS   8
#define HD      32
#define NPAIR   16            // HD/2
#define BATCH   2
#define MROWS   (BATCH*NPIX)  // 6272
#define WIN     7
#define RAD     3

// -------- scratch (static device allocations; no cudaMalloc anywhere) --------
__device__ float g_q[BATCH*HEADS*NPIX*HD];
__device__ float g_k[BATCH*HEADS*NPIX*HD];
__device__ float g_v[BATCH*HEADS*NPIX*HD];
__device__ float g_attn[BATCH*NPIX*CDIM];
__device__ float g_cos[NPIX*NPAIR];
__device__ float g_sin[NPIX*NPAIR];

// ---------------- RoPE tables (double precision, matches numpy) ----------------
__global__ void rope_table_kernel() {
    int idx = blockIdx.x * blockDim.x + threadIdx.x;
    if (idx >= NPIX * NPAIR) return;
    int p = idx & (NPAIR - 1);
    int n = idx >> 4;
    double inv = pow(10000.0, -(double)p / 16.0);
    double ang = (double)n * inv;
    double s, c;
    sincos(ang, &s, &c);
    g_cos[idx] = (float)c;
    g_sin[idx] = (float)s;
}

// ---------------- QKV GEMM (M=6272, N=768, K=256) fused with RoPE ----------------
// BM=128, BN=64, BK=16, 256 threads, 8x4 acc per thread.
__global__ void __launch_bounds__(256) qkv_rope_gemm(
    const float* __restrict__ X, const float* __restrict__ W)
{
    __shared__ float As[16][132];   // [k][m], padded
    __shared__ float Bs[16][68];    // [k][n], padded

    const int tid = threadIdx.x;
    const int mBase = blockIdx.y * 128;
    const int nBase = blockIdx.x * 64;

    const int arow = tid >> 2;            // 0..63
    const int ak4  = (tid & 3) * 4;
    const int brow = tid >> 4;            // 0..15
    const int bcol4 = (tid & 15) * 4;
    const int ty = tid >> 4;              // 0..15
    const int tx = tid & 15;              // 0..15

    float acc[8][4];
#pragma unroll
    for (int i = 0; i < 8; i++)
#pragma unroll
        for (int j = 0; j < 4; j++) acc[i][j] = 0.f;

    for (int kt = 0; kt < 256; kt += 16) {
        __syncthreads();
        float4 av0 = *(const float4*)(X + (size_t)(mBase + arow)      * 256 + kt + ak4);
        float4 av1 = *(const float4*)(X + (size_t)(mBase + arow + 64) * 256 + kt + ak4);
        As[ak4 + 0][arow] = av0.x; As[ak4 + 1][arow] = av0.y;
        As[ak4 + 2][arow] = av0.z; As[ak4 + 3][arow] = av0.w;
        As[ak4 + 0][arow + 64] = av1.x; As[ak4 + 1][arow + 64] = av1.y;
        As[ak4 + 2][arow + 64] = av1.z; As[ak4 + 3][arow + 64] = av1.w;
        float4 bv = *(const float4*)(W + (size_t)(kt + brow) * 768 + nBase + bcol4);
        *(float4*)&Bs[brow][bcol4] = bv;
        __syncthreads();

#pragma unroll
        for (int kk = 0; kk < 16; kk++) {
            float4 a0 = *(const float4*)&As[kk][ty * 8];
            float4 a1 = *(const float4*)&As[kk][ty * 8 + 4];
            float4 b  = *(const float4*)&Bs[kk][tx * 4];
            float ar[8] = {a0.x, a0.y, a0.z, a0.w, a1.x, a1.y, a1.z, a1.w};
            float br[4] = {b.x, b.y, b.z, b.w};
#pragma unroll
            for (int i = 0; i < 8; i++)
#pragma unroll
                for (int j = 0; j < 4; j++)
                    acc[i][j] = fmaf(ar[i], br[j], acc[i][j]);
        }
    }

    // epilogue: RoPE + scatter to g_q/g_k/g_v [b, head, n, d]
    const int col0 = nBase + tx * 4;         // multiple of 4; 4-col group within one head
    const int which = col0 >> 8;             // 0=q, 1=k, 2=v
    const int rem  = col0 & 255;
    const int head = rem >> 5;
    const int d0   = rem & 31;
    float* dst = (which == 0) ? g_q : (which == 1) ? g_k : g_v;

#pragma unroll
    for (int ii = 0; ii < 8; ii++) {
        int grow = mBase + ty * 8 + ii;
        int b = grow / NPIX;
        int n = grow - b * NPIX;
        size_t base = ((size_t)(b * HEADS + head) * NPIX + n) * HD + d0;
        float x0 = acc[ii][0], x1 = acc[ii][1], x2 = acc[ii][2], x3 = acc[ii][3];
        if (which < 2) {
            int p0 = d0 >> 1;
            float c0 = g_cos[n * NPAIR + p0],     s0 = g_sin[n * NPAIR + p0];
            float c1 = g_cos[n * NPAIR + p0 + 1], s1 = g_sin[n * NPAIR + p0 + 1];
            dst[base + 0] = x0 * c0 - x1 * s0;
            dst[base + 1] = x1 * c0 + x0 * s0;
            dst[base + 2] = x2 * c1 - x3 * s1;
            dst[base + 3] = x3 * c1 + x2 * s1;
        } else {
            dst[base + 0] = x0; dst[base + 1] = x1;
            dst[base + 2] = x2; dst[base + 3] = x3;
        }
    }
}

// ---------------- Neighborhood attention ----------------
// grid = (H, B*heads). Block = 256 threads (8 warps), warp per query (7 queries/warp).
// smem stages the 7x56 key/value band (fp32): 2 * 12544 floats = 100352 B.
__global__ void __launch_bounds__(256) attn_kernel() {
    extern __shared__ float sm[];
    float* ks = sm;
    float* vs = sm + WIN * HW * HD;   // 12544

    const int i  = blockIdx.x;        // query row
    const int bh = blockIdx.y;        // b*8 + h
    const int tid = threadIdx.x;
    const int w = tid >> 5;
    const int lane = tid & 31;

    const int r0 = min(max(i - RAD, 0), HW - WIN);

    const float4* k4 = (const float4*)(g_k + ((size_t)bh * NPIX + r0 * HW) * HD);
    const float4* v4 = (const float4*)(g_v + ((size_t)bh * NPIX + r0 * HW) * HD);
    float4* ks4 = (float4*)ks;
    float4* vs4 = (float4*)vs;
    for (int idx = tid; idx < WIN * HW * HD / 4; idx += 256) {
        ks4[idx] = k4[idx];
        vs4[idx] = v4[idx];
    }
    __syncthreads();

    const float scale = 0.17677669529663688f;  // 32^-0.5
    const int b = bh >> 3;
    const int h = bh & 7;

    for (int t = 0; t < WIN; t++) {
        int jq = w * WIN + t;                  // 8 warps * 7 = 56 queries
        float qv = g_q[((size_t)bh * NPIX + i * HW + jq) * HD + lane];
        int c0 = min(max(jq - RAD, 0), HW - WIN);

        float m = -1e30f, l = 0.f, o = 0.f;
        for (int rr = 0; rr < WIN; rr++) {
            int rowoff = rr * HW + c0;
#pragma unroll
            for (int cc = 0; cc < WIN; cc++) {
                int off = (rowoff + cc) * HD;
                float s = qv * ks[off + lane];
                s += __shfl_xor_sync(0xffffffffu, s, 16);
                s += __shfl_xor_sync(0xffffffffu, s, 8);
                s += __shfl_xor_sync(0xffffffffu, s, 4);
                s += __shfl_xor_sync(0xffffffffu, s, 2);
                s += __shfl_xor_sync(0xffffffffu, s, 1);
                s *= scale;
                float mn = fmaxf(m, s);
                float corr = __expf(m - mn);
                float p = __expf(s - mn);
                l = l * corr + p;
                o = o * corr + p * vs[off + lane];
                m = mn;
            }
        }
        // write [B, N, C] layout for the projection GEMM
        g_attn[((size_t)b * NPIX + i * HW + jq) * CDIM + h * HD + lane] = o / l;
    }
}

// ---------------- Projection GEMM (M=6272, N=256, K=256) + bias ----------------
__global__ void __launch_bounds__(256) proj_gemm(
    const float* __restrict__ W, const float* __restrict__ bias, float* __restrict__ out)
{
    __shared__ float As[16][132];
    __shared__ float Bs[16][68];

    const int tid = threadIdx.x;
    const int mBase = blockIdx.y * 128;
    const int nBase = blockIdx.x * 64;

    const int arow = tid >> 2;
    const int ak4  = (tid & 3) * 4;
    const int brow = tid >> 4;
    const int bcol4 = (tid & 15) * 4;
    const int ty = tid >> 4;
    const int tx = tid & 15;

    float acc[8][4];
#pragma unroll
    for (int i = 0; i < 8; i++)
#pragma unroll
        for (int j = 0; j < 4; j++) acc[i][j] = 0.f;

    for (int kt = 0; kt < 256; kt += 16) {
        __syncthreads();
        float4 av0 = *(const float4*)(g_attn + (size_t)(mBase + arow)      * 256 + kt + ak4);
        float4 av1 = *(const float4*)(g_attn + (size_t)(mBase + arow + 64) * 256 + kt + ak4);
        As[ak4 + 0][arow] = av0.x; As[ak4 + 1][arow] = av0.y;
        As[ak4 + 2][arow] = av0.z; As[ak4 + 3][arow] = av0.w;
        As[ak4 + 0][arow + 64] = av1.x; As[ak4 + 1][arow + 64] = av1.y;
        As[ak4 + 2][arow + 64] = av1.z; As[ak4 + 3][arow + 64] = av1.w;
        float4 bv = *(const float4*)(W + (size_t)(kt + brow) * 256 + nBase + bcol4);
        *(float4*)&Bs[brow][bcol4] = bv;
        __syncthreads();

#pragma unroll
        for (int kk = 0; kk < 16; kk++) {
            float4 a0 = *(const float4*)&As[kk][ty * 8];
            float4 a1 = *(const float4*)&As[kk][ty * 8 + 4];
            float4 b  = *(const float4*)&Bs[kk][tx * 4];
            float ar[8] = {a0.x, a0.y, a0.z, a0.w, a1.x, a1.y, a1.z, a1.w};
            float br[4] = {b.x, b.y, b.z, b.w};
#pragma unroll
            for (int i = 0; i < 8; i++)
#pragma unroll
                for (int j = 0; j < 4; j++)
                    acc[i][j] = fmaf(ar[i], br[j], acc[i][j]);
        }
    }

    const int col0 = nBase + tx * 4;
    float4 bv = *(const float4*)(bias + col0);
#pragma unroll
    for (int ii = 0; ii < 8; ii++) {
        int grow = mBase + ty * 8 + ii;
        float4 r;
        r.x = acc[ii][0] + bv.x;
        r.y = acc[ii][1] + bv.y;
        r.z = acc[ii][2] + bv.z;
        r.w = acc[ii][3] + bv.w;
        *(float4*)(out + (size_t)grow * 256 + col0) = r;
    }
}

// ---------------- launch ----------------
extern "C" void kernel_launch(void* const* d_in, const int* in_sizes, int n_in,
                              void* d_out, int out_size)
{
    const float* x     = (const float*)d_in[0];
    const float* Wqkv  = (const float*)d_in[1];
    const float* Wproj = (const float*)d_in[2];
    const float* bproj = (const float*)d_in[3];
    float* out = (float*)d_out;

    static bool attr_set = false;
    if (!attr_set) {
        cudaFuncSetAttribute(attn_kernel, cudaFuncAttributeMaxDynamicSharedMemorySize,
                             2 * WIN * HW * HD * (int)sizeof(float));
        attr_set = true;
    }

    rope_table_kernel<<<(NPIX * NPAIR + 255) / 256, 256>>>();
    qkv_rope_gemm<<<dim3(768 / 64, MROWS / 128), 256>>>(x, Wqkv);
    attn_kernel<<<dim3(HW, BATCH * HEADS), 256, 2 * WIN * HW * HD * (int)sizeof(float)>>>();
    proj_gemm<<<dim3(256 / 64, MROWS / 128), 256>>>(Wproj, bproj, out);
}